// round 4
// baseline (speedup 1.0000x reference)
#include <cuda_runtime.h>
#include <math.h>

#define B_   64
#define N_   4096
#define D_   128
#define E_   512
#define S_   16                 // N-splits per batch
#define GPB  32                 // 8-lane groups per block (256 thr)
#define TSTREAMS (S_*GPB)       // 512 interleaved slot streams per batch

// ---- device scratch (no allocations allowed) ----
__device__ float g_q  [B_*D_];
__device__ float g_qa [B_*D_];
__device__ int   g_cnt[B_];
__device__ float g_M;           // >= max logit (Cauchy-Schwarz bound)
__device__ float g_ba;
__device__ float g_ps [B_*S_];
__device__ float g_pacc[B_*S_*D_];

// ============================================================
// Kernel 1: proj_q = vecQ @ Wq^T + bq ; qa = q * Wa.
// Column-per-block: grid=128 (one block per output dim d).
// Wq row d loaded into smem ONCE (kills redundant L2 refetch);
// 256 threads = 64 batches x 4 K-quarters, smem reduce.
// Side duties: parallel imagesObjectNum decode; M = max(ba+||Wa||,0).
// ============================================================
__global__ void __launch_bounds__(256)
proj_kernel(const float* __restrict__ vq,
            const float* __restrict__ Wq,
            const float* __restrict__ bq,
            const float* __restrict__ Wa,
            const float* __restrict__ ba_p,
            const int*   __restrict__ ion)
{
    __shared__ float wrow[E_];
    __shared__ float part[4][B_];

    const int d   = blockIdx.x;
    const int tid = threadIdx.x;

    // load Wq[d] into smem, coalesced
    ((float2*)wrow)[tid] = ((const float2*)(Wq + (size_t)d * E_))[tid];

    // side duty A: decode imagesObjectNum (int32 vs int64 robust), parallel
    if (d == 0 && tid < 32) {
        // Values in [0,4096): if int64 (LE), every odd 32-bit word of the
        // first 64 words is 0. Detection reads stay in the first 256 bytes
        // (safe for both layouts); word 2*(tid+32) (<=504B) is read only
        // when layout is int64 (alloc is 512B).
        bool odd_zero = (ion[2*tid + 1] == 0);
        bool is64 = __all_sync(0xffffffffu, odd_zero);
        g_cnt[tid]      = is64 ? ion[2*tid]        : ion[tid];
        g_cnt[tid + 32] = is64 ? ion[2*(tid + 32)] : ion[tid + 32];
    }
    // side duty B: M = max(ba + ||Wa||, 0)  (upper bound on all logits)
    if (d == 1 && tid >= 32 && tid < 64) {
        const int lane = tid & 31;
        float t = 0.f;
        #pragma unroll
        for (int i = 0; i < 4; i++) {
            float wv = Wa[i*32 + lane];
            t += wv * wv;
        }
        #pragma unroll
        for (int off = 16; off > 0; off >>= 1)
            t += __shfl_xor_sync(0xffffffffu, t, off);
        if (lane == 0) {
            float ba = *ba_p;
            g_ba = ba;
            g_M  = fmaxf(ba + sqrtf(t), 0.f);
        }
    }
    __syncthreads();

    const int b   = tid & (B_ - 1);
    const int qtr = tid >> 6;           // K quarter (0..3)

    const float4* v4 = (const float4*)(vq + (size_t)b * E_) + qtr * 32;
    const float4* w4 = (const float4*)(wrow)                + qtr * 32;
    float a = 0.f;
    #pragma unroll
    for (int i = 0; i < 32; i++) {
        float4 x = v4[i];
        float4 y = w4[i];                // smem broadcast, conflict-free
        a += x.x*y.x + x.y*y.y + x.z*y.z + x.w*y.w;
    }
    part[qtr][b] = a;
    __syncthreads();

    if (tid < B_) {
        float qv = part[0][tid] + part[1][tid] + part[2][tid] + part[3][tid]
                 + bq[d];
        g_q [tid*D_ + d] = qv;
        g_qa[tid*D_ + d] = qv * Wa[d];
    }
}

// ============================================================
// Kernel 2: single pass over kb, fixed-reference softmax weights.
// 8-lane groups: each group owns one slot (128 floats = 16/lane).
// No online-max: w = exp(L - M), pure accumulation (no serial chain).
// grid(B*S_) = 1024 blocks x 256 threads; streams interleaved
// (stride 512) so variable per-batch counts stay balanced.
// Masked slots (n >= count) are never read. kb loads use __ldcs
// (streaming, no reuse).
// ============================================================
__global__ void __launch_bounds__(256)
att_kernel(const float* __restrict__ kb)
{
    const int bs    = blockIdx.x;
    const int b     = bs >> 4;          // / S_
    const int split = bs & (S_ - 1);
    const int warp  = threadIdx.x >> 5;
    const int lane  = threadIdx.x & 31;
    const int g     = lane >> 3;        // group within warp (0..3)
    const int sub   = lane & 7;         // lane within group
    const int gid   = warp * 4 + g;     // 0..31

    const int  cnt     = g_cnt[b];
    const int  limit   = (cnt == 0) ? N_ : cnt;
    const bool uniform = (cnt == 0);
    const float M  = g_M;
    const float ba = g_ba;

    // q,qa: this lane's 16 floats (elements i*32 + sub*4 .. +3)
    float4 q[4], qa[4];
    #pragma unroll
    for (int i = 0; i < 4; i++) {
        q[i]  = ((const float4*)(g_q  + b*D_))[i*8 + sub];
        qa[i] = ((const float4*)(g_qa + b*D_))[i*8 + sub];
    }

    const float4* kb4 = (const float4*)(kb + (size_t)b * N_ * D_);

    float  s = 0.f;
    float4 acc[4] = {make_float4(0,0,0,0), make_float4(0,0,0,0),
                     make_float4(0,0,0,0), make_float4(0,0,0,0)};
    const float4 ZERO = make_float4(0,0,0,0);

    // two slots per group per iteration for MLP
    for (int n0 = split*GPB + gid; __any_sync(0xffffffffu, n0 < limit);
         n0 += 2*TSTREAMS) {
        const int  n1 = n0 + TSTREAMS;
        const bool v0 = n0 < limit;
        const bool v1 = n1 < limit;

        float4 k0[4], k1[4];
        #pragma unroll
        for (int i = 0; i < 4; i++)
            k0[i] = v0 ? __ldcs(&kb4[(size_t)n0*32 + i*8 + sub]) : ZERO;
        #pragma unroll
        for (int i = 0; i < 4; i++)
            k1[i] = v1 ? __ldcs(&kb4[(size_t)n1*32 + i*8 + sub]) : ZERO;

        #pragma unroll
        for (int t = 0; t < 2; t++) {
            float4* k = t ? k1 : k0;
            bool    v = t ? v1 : v0;
            float dot = 0.f, nrm = 0.f;
            #pragma unroll
            for (int i = 0; i < 4; i++) {
                float px = k[i].x*q[i].x, py = k[i].y*q[i].y;
                float pz = k[i].z*q[i].z, pw = k[i].w*q[i].w;
                nrm += px*px + py*py + pz*pz + pw*pw;
                dot += k[i].x*qa[i].x + k[i].y*qa[i].y
                     + k[i].z*qa[i].z + k[i].w*qa[i].w;
            }
            #pragma unroll
            for (int off = 4; off > 0; off >>= 1) {
                dot += __shfl_xor_sync(0xffffffffu, dot, off);
                nrm += __shfl_xor_sync(0xffffffffu, nrm, off);
            }
            // dot*rsqrt(max(nrm,1e-24)) == dot/max(sqrt(nrm),1e-12)
            float L = uniform ? 0.f
                              : (dot * rsqrtf(fmaxf(nrm, 1e-24f)) + ba);
            float w = v ? __expf(L - M) : 0.f;   // L <= M always: no overflow
            s += w;
            #pragma unroll
            for (int i = 0; i < 4; i++) {
                acc[i].x += w * k[i].x;  acc[i].y += w * k[i].y;
                acc[i].z += w * k[i].z;  acc[i].w += w * k[i].w;
            }
        }
    }

    // merge 32 groups of this CTA (plain sums; 528B row stride keeps
    // 16B alignment and avoids bank conflicts)
    __shared__ float sacc[GPB][132];
    __shared__ float ssum[GPB];
    #pragma unroll
    for (int i = 0; i < 4; i++)
        *(float4*)&sacc[gid][i*32 + sub*4] = acc[i];
    if (sub == 0) ssum[gid] = s;
    __syncthreads();

    if (threadIdx.x < D_) {
        const int d = threadIdx.x;
        float a = 0.f;
        #pragma unroll
        for (int j = 0; j < GPB; j++) a += sacc[j][d];
        g_pacc[bs*D_ + d] = a;
    } else if (threadIdx.x == D_) {
        float t = 0.f;
        #pragma unroll
        for (int j = 0; j < GPB; j++) t += ssum[j];
        g_ps[bs] = t;
    }
}

// ============================================================
// Kernel 3: sum the S_ split partials, divide, write output.
// ============================================================
__global__ void combine_kernel(float* __restrict__ out)
{
    const int b = blockIdx.x;
    const int d = threadIdx.x;
    float ss = 0.f, av = 0.f;
    #pragma unroll
    for (int i = 0; i < S_; i++) {
        ss += g_ps[b*S_ + i];
        av += g_pacc[(b*S_ + i)*D_ + d];
    }
    out[b*D_ + d] = av / ss;   // ss > 0 always (limit >= 1)
}

extern "C" void kernel_launch(void* const* d_in, const int* in_sizes, int n_in,
                              void* d_out, int out_size)
{
    const float* kb  = (const float*)d_in[0];
    const float* vq  = (const float*)d_in[1];
    const int*   ion = (const int*)  d_in[2];   // int32 or int64, auto-detected
    const float* Wq  = (const float*)d_in[3];
    const float* bq  = (const float*)d_in[4];
    const float* Wa  = (const float*)d_in[5];
    const float* ba  = (const float*)d_in[6];
    float* out = (float*)d_out;

    proj_kernel   <<<D_,      256>>>(vq, Wq, bq, Wa, ba, ion);
    att_kernel    <<<B_ * S_, 256>>>(kb);
    combine_kernel<<<B_,      D_ >>>(out);
}